// round 1
// baseline (speedup 1.0000x reference)
#include <cuda_runtime.h>

// filtfilt(butter(4,0.2)) over 512 rows x 48000 fp32, with per-row max-abs
// normalization and odd-reflection padding (padlen 15).
//
// Strategy: the dominant pole radius is ~0.8854, so IIR state decays below
// fp32 epsilon within ~250 samples. Each pass (forward, backward) is split
// into independent 512-sample chunks, each warmed up from zero state over the
// preceding 256 samples (exact x-history, approximated-to-zero y-history).
// 512 rows x 94 chunks = 48128 independent threads per pass.

namespace {
constexpr int kRows  = 512;
constexpr int kT     = 48000;
constexpr int kPad   = 15;
constexpr int kP     = kT + 2 * kPad;     // 48030 padded length
constexpr int kChunk = 512;
constexpr int kWarm  = 256;
constexpr int kNch   = (kP + kChunk - 1) / kChunk;  // 94

constexpr float B0 = 0.004824343357716228f;
constexpr float B1 = 0.019297373430864913f;
constexpr float B2 = 0.02894606014629737f;
// b3 == B1, b4 == B0 (binomial), a0 == 1
constexpr float A1 = -2.369513007182038f;
constexpr float A2 = 2.3139884144006455f;
constexpr float A3 = -1.0546654058785672f;
constexpr float A4 = 0.18737949236818502f;
}  // namespace

// Scratch: forward-pass output over the padded signal, plus per-row scales.
__device__ float g_y1[(size_t)kRows * kP];
__device__ float g_scale[kRows];
__device__ float g_inv[kRows];

// ---------------------------------------------------------------------------
// Kernel 1: per-row max(|x|)
// ---------------------------------------------------------------------------
__global__ void k_maxabs(const float* __restrict__ x) {
    int row = blockIdx.x;
    const float4* xr = reinterpret_cast<const float4*>(x + (size_t)row * kT);
    float m = 0.f;
    for (int i = threadIdx.x; i < kT / 4; i += 256) {
        float4 v = __ldg(xr + i);
        m = fmaxf(m, fmaxf(fmaxf(fabsf(v.x), fabsf(v.y)),
                           fmaxf(fabsf(v.z), fabsf(v.w))));
    }
    #pragma unroll
    for (int o = 16; o; o >>= 1) m = fmaxf(m, __shfl_xor_sync(0xffffffffu, m, o));
    __shared__ float sm[8];
    if ((threadIdx.x & 31) == 0) sm[threadIdx.x >> 5] = m;
    __syncthreads();
    if (threadIdx.x < 8) {
        m = sm[threadIdx.x];
        #pragma unroll
        for (int o = 4; o; o >>= 1) m = fmaxf(m, __shfl_xor_sync(0xffu, m, o));
        if (threadIdx.x == 0) {
            g_scale[row] = m;
            g_inv[row]   = 1.0f / m;
        }
    }
}

// ---------------------------------------------------------------------------
// Padded-signal access (forward pass). n is a padded-coordinate index.
// Returns RAW (unscaled) values; scaling is folded into the b coefficients.
//   n < 0            : lfilter zero front-pad
//   0   <= n < 15    : 2*x[0]   - x[14 - n]
//   15  <= n < 15+T  : x[n-15]
//   15+T<= n < P     : 2*x[T-1] - x[2T + 12 - n]
// ---------------------------------------------------------------------------
__device__ __forceinline__ float xp_load(const float* __restrict__ xr, int n) {
    if (n < 0) return 0.f;
    if (n < kPad) return 2.f * xr[0] - xr[14 - n];
    int m = n - kPad;
    if (m < kT) return xr[m];
    return 2.f * xr[kT - 1] - xr[2 * kT + 12 - n];
}

// ---------------------------------------------------------------------------
// Forward chunk: y[n] = sum b'_k * xp[n-k] - sum a_k * y[n-k]
// with b' = b * inv_scale. Warm-up [ws, s) discarded, [s, e) stored.
// ---------------------------------------------------------------------------
template <bool EDGE>
__device__ __forceinline__ void fwd_body(const float* __restrict__ xr,
                                         float* __restrict__ yr,
                                         float inv, int s, int e) {
    const float b0 = B0 * inv, b1 = B1 * inv, b2 = B2 * inv;
    int ws = s - kWarm;
    if (ws < 0) ws = 0;
    const float* __restrict__ xq = xr - kPad;  // xq[n] == x[n - 15]

    float h0, h1, h2, h3;  // xp[n-1] .. xp[n-4]
    if (EDGE) {
        h0 = xp_load(xr, ws - 1); h1 = xp_load(xr, ws - 2);
        h2 = xp_load(xr, ws - 3); h3 = xp_load(xr, ws - 4);
    } else {
        h0 = xq[ws - 1]; h1 = xq[ws - 2]; h2 = xq[ws - 3]; h3 = xq[ws - 4];
    }
    float y1 = 0.f, y2 = 0.f, y3 = 0.f, y4 = 0.f;

    #pragma unroll 4
    for (int n = ws; n < s; ++n) {
        float xn = EDGE ? xp_load(xr, n) : xq[n];
        float f = fmaf(b0, xn, fmaf(b1, h0, fmaf(b2, h1, fmaf(b1, h2, b0 * h3))));
        float y = fmaf(-A4, y4, f);
        y = fmaf(-A3, y3, y);
        y = fmaf(-A2, y2, y);
        y = fmaf(-A1, y1, y);
        h3 = h2; h2 = h1; h1 = h0; h0 = xn;
        y4 = y3; y3 = y2; y2 = y1; y1 = y;
    }
    #pragma unroll 4
    for (int n = s; n < e; ++n) {
        float xn = EDGE ? xp_load(xr, n) : xq[n];
        float f = fmaf(b0, xn, fmaf(b1, h0, fmaf(b2, h1, fmaf(b1, h2, b0 * h3))));
        float y = fmaf(-A4, y4, f);
        y = fmaf(-A3, y3, y);
        y = fmaf(-A2, y2, y);
        y = fmaf(-A1, y1, y);
        h3 = h2; h2 = h1; h1 = h0; h0 = xn;
        y4 = y3; y3 = y2; y2 = y1; y1 = y;
        yr[n] = y;
    }
}

__global__ void k_fwd(const float* __restrict__ x) {
    int t = blockIdx.x * blockDim.x + threadIdx.x;
    if (t >= kRows * kNch) return;
    int row = t / kNch;
    int ch  = t - row * kNch;
    const float* xr = x + (size_t)row * kT;
    float* yr = g_y1 + (size_t)row * kP;
    float inv = g_inv[row];
    int s = ch * kChunk;
    int e = min(s + kChunk, kP);
    if (ch == 0 || ch == kNch - 1) fwd_body<true>(xr, yr, inv, s, e);
    else                           fwd_body<false>(xr, yr, inv, s, e);
}

// ---------------------------------------------------------------------------
// Backward chunk (the flipped second lfilter, written as a descending
// recurrence): y2[n] = sum b_k * y1[n+k] - sum a_k * y2[n+k], n = P-1 .. 0,
// with y1[idx] == 0 for idx >= P. Warm-up (e-1, n0] discarded, [s, e) stored
// (to the final output, times scale, for padded n in [15, 15+T)).
// ---------------------------------------------------------------------------
template <bool EDGE>
__device__ __forceinline__ void bwd_body(const float* __restrict__ yr,
                                         float* __restrict__ outr,
                                         float scale, int s, int e) {
    int n0 = e - 1 + kWarm;
    if (n0 > kP - 1) n0 = kP - 1;

    float h0, h1, h2, h3;  // y1[n+1] .. y1[n+4]
    if (EDGE) {
        h0 = (n0 + 1 < kP) ? yr[n0 + 1] : 0.f;
        h1 = (n0 + 2 < kP) ? yr[n0 + 2] : 0.f;
        h2 = (n0 + 3 < kP) ? yr[n0 + 3] : 0.f;
        h3 = (n0 + 4 < kP) ? yr[n0 + 4] : 0.f;
    } else {
        h0 = yr[n0 + 1]; h1 = yr[n0 + 2]; h2 = yr[n0 + 3]; h3 = yr[n0 + 4];
    }
    float y1 = 0.f, y2 = 0.f, y3 = 0.f, y4 = 0.f;

    #pragma unroll 4
    for (int n = n0; n >= e; --n) {
        float vn = yr[n];
        float f = fmaf(B0, vn, fmaf(B1, h0, fmaf(B2, h1, fmaf(B1, h2, B0 * h3))));
        float y = fmaf(-A4, y4, f);
        y = fmaf(-A3, y3, y);
        y = fmaf(-A2, y2, y);
        y = fmaf(-A1, y1, y);
        h3 = h2; h2 = h1; h1 = h0; h0 = vn;
        y4 = y3; y3 = y2; y2 = y1; y1 = y;
    }
    #pragma unroll 4
    for (int n = e - 1; n >= s; --n) {
        float vn = yr[n];
        float f = fmaf(B0, vn, fmaf(B1, h0, fmaf(B2, h1, fmaf(B1, h2, B0 * h3))));
        float y = fmaf(-A4, y4, f);
        y = fmaf(-A3, y3, y);
        y = fmaf(-A2, y2, y);
        y = fmaf(-A1, y1, y);
        h3 = h2; h2 = h1; h1 = h0; h0 = vn;
        y4 = y3; y3 = y2; y2 = y1; y1 = y;
        if (!EDGE) {
            outr[n - kPad] = y * scale;
        } else if (n >= kPad && n < kPad + kT) {
            outr[n - kPad] = y * scale;
        }
    }
}

__global__ void k_bwd(float* __restrict__ out) {
    int t = blockIdx.x * blockDim.x + threadIdx.x;
    if (t >= kRows * kNch) return;
    int row = t / kNch;
    int ch  = t - row * kNch;
    const float* yr = g_y1 + (size_t)row * kP;
    float* outr = out + (size_t)row * kT;
    float scale = g_scale[row];
    int s = ch * kChunk;
    int e = min(s + kChunk, kP);
    if (ch == 0 || ch == kNch - 1) bwd_body<true>(yr, outr, scale, s, e);
    else                           bwd_body<false>(yr, outr, scale, s, e);
}

// ---------------------------------------------------------------------------
extern "C" void kernel_launch(void* const* d_in, const int* in_sizes, int n_in,
                              void* d_out, int out_size) {
    const float* x = (const float*)d_in[0];
    float* out = (float*)d_out;

    k_maxabs<<<kRows, 256>>>(x);

    int total  = kRows * kNch;
    int block  = 128;
    int grid   = (total + block - 1) / block;
    k_fwd<<<grid, block>>>(x);
    k_bwd<<<grid, block>>>(out);
}